// round 11
// baseline (speedup 1.0000x reference)
#include <cuda_runtime.h>
#include <cuda_bf16.h>
#include <math.h>
#include <stdint.h>

#define SEQ_LEN 16384
#define BATCH   32
#define DM      128
#define HN      256
#define THRESH  0.001f
#define EPS_GAP 2e-4f
#define EPS_TH  1e-5f

#define RPB  128            // rows per CTA
#define NBLK (SEQ_LEN/RPB)  // 128 CTAs
#define TPB  256            // 8 warps: 2 (m) x 4 (n), warp tile m64 x n64

// ---- smem word (u32) layout ----
#define AW     20               // A row stride in words (40 bf16) -> conflict-free
#define BW     20
#define ACOMP  (RPB*AW)         // 2560 words per A comp
#define BCOMP  (HN*BW)          // 5120 words per B comp
#define OFF_B  (3*ACOMP)        // 7680
#define DW     258              // D row stride words (D overlays operand region)
#define DSZ_W  (RPB*DW)         // 33024 words
#define MP_W   DSZ_W            // 128 mask-penalty floats
#define BM_W   (MP_W + RPB)     // 128 x 8 u32 bitmap
#define CNT_W  (BM_W + RPB*8)   // 1 flag counter
#define LIST_W (CNT_W + 1)      // up to 128 flagged rows
#define SMEM_W (LIST_W + RPB)
#define SMEM_B (SMEM_W*4)       // ~137.2 KB

static __device__ __forceinline__ uint32_t pk(__nv_bfloat16 a, __nv_bfloat16 b) {
    __nv_bfloat162 h = __halves2bfloat162(a, b);
    return *reinterpret_cast<uint32_t*>(&h);
}

static __device__ __forceinline__ void mma_bf16(float* c, const uint32_t* a, const uint32_t* b) {
    asm("mma.sync.aligned.m16n8k16.row.col.f32.bf16.bf16.f32 "
        "{%0,%1,%2,%3}, {%4,%5,%6,%7}, {%8,%9}, {%0,%1,%2,%3};"
        : "+f"(c[0]), "+f"(c[1]), "+f"(c[2]), "+f"(c[3])
        : "r"(a[0]), "r"(a[1]), "r"(a[2]), "r"(a[3]), "r"(b[0]), "r"(b[1]));
}

static __device__ __forceinline__ void split3(float v, __nv_bfloat16& c0,
                                              __nv_bfloat16& c1, __nv_bfloat16& c2) {
    c0 = __float2bfloat16_rn(v);
    float r1 = v - __bfloat162float(c0);
    c1 = __float2bfloat16_rn(r1);
    float r2 = r1 - __bfloat162float(c1);
    c2 = __float2bfloat16_rn(r2);
}

// Exact recompute of one flagged row by a full warp. Sequential fp32 FMA chains
// (same rounding as the rel_err==0.0 FFMA kernels) + proven warp top-8/softmax.
// Lane owns h = lane + 32*j.
static __device__ void fixup_row(int gr, int r, float pen, int lane,
                                 const float* __restrict__ node,
                                 const float* __restrict__ hyper, uint32_t* sm)
{
    float x[8];
    const float* nr = node + (size_t)gr * DM;
#pragma unroll
    for (int j = 0; j < 8; ++j) {
        const float* hr = hyper + (size_t)(lane + 32 * j) * DM;
        float s = 0.0f;
#pragma unroll 8
        for (int k = 0; k < DM; ++k) s = fmaf(__ldg(nr + k), __ldg(hr + k), s);
        x[j] = fmaxf(s, 0.0f) * pen;
    }
    unsigned ub[8];
#pragma unroll
    for (int j = 0; j < 8; ++j) ub[j] = (x[j] == 0.0f) ? 0u : __float_as_uint(x[j]);

    unsigned lmb = ub[0];
#pragma unroll
    for (int j = 1; j < 8; ++j) lmb = (ub[j] > lmb) ? ub[j] : lmb;
    float rowmax = __uint_as_float(__reduce_max_sync(0xffffffffu, lmb));

    float e[8], ls = 0.0f;
#pragma unroll
    for (int j = 0; j < 8; ++j) { e[j] = expf(x[j] - rowmax); ls += e[j]; }
#pragma unroll
    for (int o = 16; o; o >>= 1) ls += __shfl_xor_sync(0xffffffffu, ls, o);

    // exact top-8: repeated warp argmax on (value desc, h asc)
    unsigned selmask = 0;
    int bj = 0; unsigned bv = ub[0];
#pragma unroll
    for (int j = 1; j < 8; ++j) if (ub[j] > bv) { bv = ub[j]; bj = j; }
#pragma unroll 1
    for (int it = 0; it < 8; ++it) {
        unsigned cand = (bj >= 0) ? bv : 0u;
        unsigned g  = __reduce_max_sync(0xffffffffu, cand);
        unsigned hc = (bj >= 0 && cand == g) ? (unsigned)(bj * 32 + lane) : 0xffffffffu;
        unsigned gh = __reduce_min_sync(0xffffffffu, hc);
        if (hc == gh) {
            selmask |= (1u << bj);
            bv = 0u; bj = -1;
#pragma unroll
            for (int j = 0; j < 8; ++j)
                if (!(selmask & (1u << j)) && (bj < 0 || ub[j] > bv)) { bv = ub[j]; bj = j; }
        }
    }
#pragma unroll
    for (int j = 0; j < 8; ++j) {
        bool sel = ((selmask >> j) & 1u) && (e[j] / ls > THRESH);
        unsigned wv = __ballot_sync(0xffffffffu, sel);   // bit position = lane, h = lane+32j
        if (lane == 0) sm[BM_W + r * 8 + j] = wv;
    }
}

__global__ __launch_bounds__(TPB, 1)
void hg_kernel(const float* __restrict__ mask, const float* __restrict__ node,
               const float* __restrict__ hyper, float* __restrict__ out)
{
    extern __shared__ uint32_t sm[];
    float* smf = reinterpret_cast<float*>(sm);

    const int t    = threadIdx.x;
    const int n0   = blockIdx.x * RPB;
    const int lane = t & 31;
    const int w    = t >> 5;
    const int g    = lane >> 2;
    const int t4   = lane & 3;
    const int wn   = w & 3;
    const int wm   = w >> 2;

    if (t == 0) sm[CNT_W] = 0;
    if (t < RPB) {
        float s = 0.0f;
        const float* mc = mask + n0 + t;
#pragma unroll
        for (int b = 0; b < BATCH; ++b) s += mc[b * SEQ_LEN];
        smf[MP_W + t] = s / 32.0f;
    }

    float acc[4][8][4];
#pragma unroll
    for (int i = 0; i < 4; ++i)
#pragma unroll
        for (int s = 0; s < 8; ++s)
#pragma unroll
            for (int q = 0; q < 4; ++q) acc[i][s][q] = 0.0f;

    const int PA[6] = {0, 0, 1, 1, 0, 2};
    const int PB[6] = {0, 1, 0, 1, 2, 0};

    const uint32_t* Ab = sm + (64 * wm + g) * AW + t4;
    const uint32_t* Bb = sm + OFF_B + (64 * wn + g) * BW + t4;

#pragma unroll 1
    for (int ch = 0; ch < 4; ++ch) {
        __syncthreads();
        for (int i = t; i < RPB * 16; i += TPB) {
            int r = i >> 4, kp = i & 15;
            float2 v = *reinterpret_cast<const float2*>(
                node + (size_t)(n0 + r) * DM + ch * 32 + 2 * kp);
            __nv_bfloat16 x0, x1, x2, y0, y1, y2;
            split3(v.x, x0, x1, x2);
            split3(v.y, y0, y1, y2);
            int idx = r * AW + kp;
            sm[idx]             = pk(x0, y0);
            sm[ACOMP + idx]     = pk(x1, y1);
            sm[2 * ACOMP + idx] = pk(x2, y2);
        }
        for (int i = t; i < HN * 16; i += TPB) {
            int h = i >> 4, kp = i & 15;
            float2 v = *reinterpret_cast<const float2*>(
                hyper + (size_t)h * DM + ch * 32 + 2 * kp);
            __nv_bfloat16 x0, x1, x2, y0, y1, y2;
            split3(v.x, x0, x1, x2);
            split3(v.y, y0, y1, y2);
            int idx = OFF_B + h * BW + kp;
            sm[idx]             = pk(x0, y0);
            sm[BCOMP + idx]     = pk(x1, y1);
            sm[2 * BCOMP + idx] = pk(x2, y2);
        }
        __syncthreads();

#pragma unroll 1
        for (int p = 0; p < 6; ++p) {
            const uint32_t* Ap = Ab + PA[p] * ACOMP;
            const uint32_t* Bp = Bb + PB[p] * BCOMP;
#pragma unroll
            for (int ks = 0; ks < 2; ++ks) {
                uint32_t af[4][4], bf[8][2];
#pragma unroll
                for (int i = 0; i < 4; ++i) {
                    af[i][0] = Ap[i * 16 * AW + ks * 8];
                    af[i][1] = Ap[i * 16 * AW + 8 * AW + ks * 8];
                    af[i][2] = Ap[i * 16 * AW + ks * 8 + 4];
                    af[i][3] = Ap[i * 16 * AW + 8 * AW + ks * 8 + 4];
                }
#pragma unroll
                for (int s = 0; s < 8; ++s) {
                    bf[s][0] = Bp[s * 8 * BW + ks * 8];
                    bf[s][1] = Bp[s * 8 * BW + ks * 8 + 4];
                }
#pragma unroll
                for (int i = 0; i < 4; ++i)
#pragma unroll
                    for (int s = 0; s < 8; ++s) mma_bf16(acc[i][s], af[i], bf[s]);
            }
        }
    }

    __syncthreads();   // mainloop done everywhere -> overwrite operands with D

#pragma unroll
    for (int i = 0; i < 4; ++i)
#pragma unroll
        for (int s = 0; s < 8; ++s) {
            int r0 = 64 * wm + 16 * i + g;
            int c  = 64 * wn + 8 * s + 2 * t4;
            *reinterpret_cast<float2*>(&smf[r0 * DW + c]) =
                make_float2(acc[i][s][0], acc[i][s][1]);
            *reinterpret_cast<float2*>(&smf[(r0 + 8) * DW + c]) =
                make_float2(acc[i][s][2], acc[i][s][3]);
        }
    __syncthreads();

    // ---- per-row epilogue with margin detection ----
    if (t < RPB) {
        const float pen = smf[MP_W + t];
        const float* row = smf + t * DW;

        // top-9 keys (ascending): key = vbits<<8 | (255-h)  (jax ties: lower h wins)
        unsigned long long k9[9] = {0, 0, 0, 0, 0, 0, 0, 0, 0};
#pragma unroll 4
        for (int h = 0; h < HN; ++h) {
            float x = fmaxf(row[h], 0.0f) * pen;
            unsigned vb = (x == 0.0f) ? 0u : __float_as_uint(x);
            unsigned long long key = ((unsigned long long)vb << 8)
                                   | (unsigned long long)(255 - h);
            if (key > k9[0]) {
                int j = 0;
#pragma unroll
                for (int q = 0; q < 8; ++q)
                    if (key > k9[q + 1]) { k9[q] = k9[q + 1]; j = q + 1; }
                k9[j] = key;
            }
        }
        float rowmax = __uint_as_float((unsigned)(k9[8] >> 8));
        float val8   = __uint_as_float((unsigned)(k9[1] >> 8));
        float val9   = __uint_as_float((unsigned)(k9[0] >> 8));

        float Z = 0.0f;
#pragma unroll 4
        for (int h = 0; h < HN; ++h) {
            float x = fmaxf(row[h], 0.0f) * pen;
            Z += expf(x - rowmax);
        }

        bool flag = (val8 - val9 < EPS_GAP);
        unsigned bits[8] = {0, 0, 0, 0, 0, 0, 0, 0};
#pragma unroll
        for (int j = 1; j < 9; ++j) {
            float v = __uint_as_float((unsigned)(k9[j] >> 8));
            int h = 255 - (int)(k9[j] & 255ull);
            float soft = expf(v - rowmax) / Z;
            if (fabsf(soft - THRESH) < EPS_TH) flag = true;
            if (soft > THRESH) bits[h >> 5] |= 1u << (h & 31);
        }
#pragma unroll
        for (int q = 0; q < 8; ++q) sm[BM_W + t * 8 + q] = bits[q];
        if (flag) {
            int idx = atomicAdd(reinterpret_cast<int*>(&sm[CNT_W]), 1);
            sm[LIST_W + idx] = (uint32_t)t;
        }
    }
    __syncthreads();

    // ---- exact fixup of flagged rows (one warp per row) ----
    {
        int cnt = (int)sm[CNT_W];
        for (int idx = w; idx < cnt; idx += TPB / 32) {
            int r = (int)sm[LIST_W + idx];
            fixup_row(n0 + r, r, smf[MP_W + r], lane, node, hyper, sm);
        }
    }
    __syncthreads();

    // ---- coalesced output ----
    for (int i = t; i < RPB * 64; i += TPB) {
        int r = i >> 6, q = i & 63;
        int h0 = 4 * q;
        uint32_t b = sm[BM_W + r * 8 + (h0 >> 5)];
        float4 f;
        f.x = (b >> (h0 & 31))       & 1u ? 1.0f : 0.0f;
        f.y = (b >> ((h0 + 1) & 31)) & 1u ? 1.0f : 0.0f;
        f.z = (b >> ((h0 + 2) & 31)) & 1u ? 1.0f : 0.0f;
        f.w = (b >> ((h0 + 3) & 31)) & 1u ? 1.0f : 0.0f;
        *reinterpret_cast<float4*>(out + (size_t)(n0 + r) * HN + h0) = f;
    }
}

extern "C" void kernel_launch(void* const* d_in, const int* in_sizes, int n_in,
                              void* d_out, int out_size)
{
    // metadata order: [0] features (unused), [1] mask, [2] node_embeds, [3] hyper_embeds
    const float* mask  = (const float*)d_in[1];
    const float* node  = (const float*)d_in[2];
    const float* hyper = (const float*)d_in[3];
    float* out = (float*)d_out;

    cudaFuncSetAttribute(hg_kernel, cudaFuncAttributeMaxDynamicSharedMemorySize, SMEM_B);
    hg_kernel<<<NBLK, TPB, SMEM_B>>>(mask, node, hyper, out);
}

// round 13
// speedup vs baseline: 3.7060x; 3.7060x over previous
#include <cuda_runtime.h>
#include <math.h>

#define SEQ_LEN 16384
#define BATCH   32
#define DM      128
#define HN      256
#define THRESH  0.001f

#define RPB     128                 // rows per block
#define NBLK    (SEQ_LEN / RPB)     // 128 blocks
#define TPB     1024                // 32 warps, 4 rows per warp
#define KCHUNK  64                  // hyper tile k-chunk

#define NDS     264                 // floats per k-row of duplicated node (1056 B)
#define HST     258                 // floats per kk-row of hyper chunk (1032 B)
#define NODE_F  (DM * NDS)          // 33792 floats (135168 B)
#define HYP_F   (KCHUNK * HST)      // 16512 floats (66048 B)
#define SMEM_F  (NODE_F + HYP_F + RPB)
#define SMEM_B  (SMEM_F * 4)        // 201728 B

typedef unsigned long long ull;

__device__ __forceinline__ void fma2(ull& acc, ull a, ull b) {
    asm("fma.rn.f32x2 %0, %1, %2, %0;" : "+l"(acc) : "l"(a), "l"(b));
}

// One output row. Lane owns h: element e (0..7) -> h = 64*(e>>1) + 2*lane + (e&1).
// relu*maskmean -> softmax -> exact top-8 (jax ties: lowest h wins) -> threshold.
__device__ __forceinline__ void process_row(int row, const float* vin, float m,
                                            int lane, float* __restrict__ out)
{
    float v[8];
    unsigned ub[8];
#pragma unroll
    for (int e = 0; e < 8; ++e) {
        float x = fmaxf(vin[e], 0.0f) * m;
        v[e] = x;
        ub[e] = (x == 0.0f) ? 0u : __float_as_uint(x);   // nonneg: bits order-monotone
    }

    unsigned lmb = ub[0];
#pragma unroll
    for (int e = 1; e < 8; ++e) lmb = (ub[e] > lmb) ? ub[e] : lmb;
    unsigned gmb = __reduce_max_sync(0xffffffffu, lmb);
    float rowmax = __uint_as_float(gmb);

    float ex[8];
    float ls = 0.0f;
#pragma unroll
    for (int e = 0; e < 8; ++e) { ex[e] = expf(v[e] - rowmax); ls += ex[e]; }
#pragma unroll
    for (int o = 16; o; o >>= 1) ls += __shfl_xor_sync(0xffffffffu, ls, o);

    // exact top-8: repeated warp argmax on (value desc, h asc)
    unsigned selmask = 0;
    int be = 0; unsigned bv = ub[0];
#pragma unroll
    for (int e = 1; e < 8; ++e) if (ub[e] > bv) { bv = ub[e]; be = e; }
#pragma unroll 1
    for (int it = 0; it < 8; ++it) {
        unsigned cand = (be >= 0) ? bv : 0u;
        unsigned g  = __reduce_max_sync(0xffffffffu, cand);
        unsigned hc = (be >= 0 && cand == g)
                      ? (unsigned)(64 * (be >> 1) + 2 * lane + (be & 1)) : 0xffffffffu;
        unsigned gh = __reduce_min_sync(0xffffffffu, hc);
        if (hc == gh) {
            selmask |= (1u << be);
            bv = 0u; be = -1;
#pragma unroll
            for (int e = 0; e < 8; ++e)
                if (!(selmask & (1u << e)) && (be < 0 || ub[e] > bv)) { bv = ub[e]; be = e; }
        }
    }

    float* op = out + (size_t)row * HN + 2 * lane;
#pragma unroll
    for (int j = 0; j < 4; ++j) {
        float2 r2;
        r2.x = (((selmask >> (2 * j)) & 1u)     && (ex[2 * j]     / ls > THRESH)) ? 1.0f : 0.0f;
        r2.y = (((selmask >> (2 * j + 1)) & 1u) && (ex[2 * j + 1] / ls > THRESH)) ? 1.0f : 0.0f;
        *reinterpret_cast<float2*>(op + 64 * j) = r2;
    }
}

__global__ __launch_bounds__(TPB, 1)
void hg_kernel(const float* __restrict__ mask, const float* __restrict__ node,
               const float* __restrict__ hyper, float* __restrict__ out)
{
    extern __shared__ float sm[];
    float* node_sh = sm;                    // [DM][NDS] : node_sh[k*NDS + 2r] = node_sh[..+2r+1] = node[r][k]
    float* hyp_sh  = sm + NODE_F;           // [KCHUNK][HST] : hyp_sh[kk*HST + h]
    float* mp_sh   = sm + NODE_F + HYP_F;   // [RPB]

    const int t  = threadIdx.x;
    const int n0 = blockIdx.x * RPB;

    // batch-mean mask penalty (sequential b order, matches jax)
    if (t < RPB) {
        float s = 0.0f;
        const float* mc = mask + n0 + t;
#pragma unroll
        for (int b = 0; b < BATCH; ++b) s += mc[b * SEQ_LEN];
        mp_sh[t] = s / 32.0f;
    }
    // node tile, k-major, duplicated along rows (coalesced global reads)
    for (int i = t; i < RPB * DM; i += TPB) {
        int r = i >> 7, d = i & (DM - 1);
        float v = node[(size_t)(n0 + r) * DM + d];
        node_sh[d * NDS + 2 * r]     = v;
        node_sh[d * NDS + 2 * r + 1] = v;
    }

    const int lane = t & 31;
    const int w    = t >> 5;                 // 0..31, warp owns rows [4w, 4w+4)

    // acc[r][j]: f32x2 { sim(row 4w+r, h=64j+2lane), sim(row, h+1) }
    // each half is a plain sequential fp32 FMA chain over k (matches jax rounding).
    ull acc[4][4];
#pragma unroll
    for (int r = 0; r < 4; ++r)
#pragma unroll
        for (int j = 0; j < 4; ++j) acc[r][j] = 0ull;

#pragma unroll 1
    for (int c = 0; c < 2; ++c) {
        __syncthreads();   // c=1: all warps done reading chunk 0
        // hyper chunk c, k-major (coalesced: consecutive t -> consecutive kk)
        for (int i = t; i < HN * KCHUNK; i += TPB) {
            int h = i >> 6, kk = i & (KCHUNK - 1);
            hyp_sh[kk * HST + h] = hyper[(size_t)h * DM + c * KCHUNK + kk];
        }
        __syncthreads();   // chunk (and, at c=0, node/mp tiles) visible

        const float* nrow = node_sh + c * KCHUNK * NDS + 8 * w;
        const float* hrow = hyp_sh + 2 * lane;
#pragma unroll 4
        for (int kk = 0; kk < KCHUNK; ++kk) {
            // 4 dup-pairs for rows 4w..4w+3 : 2x LDS.128 (broadcast)
            ulonglong2 q0 = *reinterpret_cast<const ulonglong2*>(nrow);
            ulonglong2 q1 = *reinterpret_cast<const ulonglong2*>(nrow + 4);
            ull nd[4] = { q0.x, q0.y, q1.x, q1.y };
            // 4 adjacent-h pairs : 4x LDS.64 (conflict-free)
            ull hs[4];
#pragma unroll
            for (int j = 0; j < 4; ++j)
                hs[j] = *reinterpret_cast<const ull*>(hrow + 64 * j);
#pragma unroll
            for (int r = 0; r < 4; ++r)
#pragma unroll
                for (int j = 0; j < 4; ++j) fma2(acc[r][j], nd[r], hs[j]);
            nrow += NDS;
            hrow += HST;
        }
    }

    // epilogue: fully static acc indexing; warp handles its 4 rows
#pragma unroll
    for (int r = 0; r < 4; ++r) {
        float vin[8];
#pragma unroll
        for (int j = 0; j < 4; ++j) {
            vin[2 * j]     = __uint_as_float((unsigned)(acc[r][j] & 0xffffffffull));
            vin[2 * j + 1] = __uint_as_float((unsigned)(acc[r][j] >> 32));
        }
        int rr = 4 * w + r;
        process_row(n0 + rr, vin, mp_sh[rr], lane, out);
    }
}

extern "C" void kernel_launch(void* const* d_in, const int* in_sizes, int n_in,
                              void* d_out, int out_size)
{
    // metadata order: [0] features (unused), [1] mask, [2] node_embeds, [3] hyper_embeds
    const float* mask  = (const float*)d_in[1];
    const float* node  = (const float*)d_in[2];
    const float* hyper = (const float*)d_in[3];
    float* out = (float*)d_out;

    cudaFuncSetAttribute(hg_kernel, cudaFuncAttributeMaxDynamicSharedMemorySize, SMEM_B);
    hg_kernel<<<NBLK, TPB, SMEM_B>>>(mask, node, hyper, out);
}